// round 1
// baseline (speedup 1.0000x reference)
#include <cuda_runtime.h>

#define NN 50000
#define EE 800000
#define DDIM 128
#define HH 128
#define GG 500
#define FC1 64
#define EPSBN 1e-5f
#define STAT_NB 240

// ---------------- device scratch (static, no allocation) ----------------
__device__ float g_h[NN * HH];      // GEMM output (pre-aggregation)
__device__ float g_agg[NN * HH];    // aggregated output (pre-BN)
__device__ int   g_cnt[NN];
__device__ int   g_fill[NN];
__device__ int   g_ptr[NN + 1];
__device__ float g_dis[NN];
__device__ int   g_csr_src[EE];
__device__ float g_csr_w[EE];
__device__ float g_psum[STAT_NB * HH];
__device__ float g_psq[STAT_NB * HH];
__device__ float g_bn_a[HH];
__device__ float g_bn_b[HH];
__device__ int   g_gcnt[GG];
__device__ int   g_goff[GG + 1];
__device__ float g_pooled[GG * HH];
__device__ float g_z[GG * FC1];
__device__ float g_fc_a[FC1];
__device__ float g_fc_b[FC1];
__device__ int   g_is64;

// ---------------- helpers ----------------
__device__ __forceinline__ int ld_idx(const void* p, long long i, int is64) {
    return is64 ? (int)(((const long long*)p)[i]) : ((const int*)p)[i];
}

// detect whether index arrays are int64 (hi words of first 256 pairs all zero)
__global__ void k_detect(const void* eidx) {
    __shared__ int any;
    const int* p = (const int*)eidx;
    if (threadIdx.x == 0) any = 0;
    __syncthreads();
    if (p[2 * threadIdx.x + 1] != 0) atomicOr(&any, 1);
    __syncthreads();
    if (threadIdx.x == 0) g_is64 = any ? 0 : 1;
}

__global__ void k_zero() {
    int i = blockIdx.x * blockDim.x + threadIdx.x;
    if (i < NN) { g_cnt[i] = 0; g_fill[i] = 0; }
    if (i < GG) g_gcnt[i] = 0;
}

__global__ void k_count(const void* eidx) {
    int e = blockIdx.x * blockDim.x + threadIdx.x;
    if (e >= EE) return;
    int is64 = g_is64;
    int d = ld_idx(eidx, (long long)EE + e, is64);
    atomicAdd(&g_cnt[d], 1);
}

__global__ void k_gcount(const void* batch) {
    int i = blockIdx.x * blockDim.x + threadIdx.x;
    if (i >= NN) return;
    int is64 = g_is64;
    int b = ld_idx(batch, i, is64);
    atomicAdd(&g_gcnt[b], 1);
}

// single-block exclusive scan over N node counts; also writes dis = rsqrt(deg)
__global__ void k_scan() {
    const int CH = 49;  // 1024*49 = 50176 >= NN
    __shared__ int sm[1024];
    int t = threadIdx.x;
    int base = t * CH;
    int len = NN - base;
    if (len < 0) len = 0;
    if (len > CH) len = CH;
    int s = 0;
    for (int i = 0; i < len; i++) s += g_cnt[base + i];
    sm[t] = s;
    __syncthreads();
    for (int off = 1; off < 1024; off <<= 1) {
        int v = (t >= off) ? sm[t - off] : 0;
        __syncthreads();
        sm[t] += v;
        __syncthreads();
    }
    int run = sm[t] - s;  // exclusive prefix
    for (int i = 0; i < len; i++) {
        int c = g_cnt[base + i];
        g_ptr[base + i] = run;
        g_dis[base + i] = rsqrtf((float)(c + 1));  // +1 self loop, deg>=1
        run += c;
    }
    if (base < NN && base + CH >= NN) g_ptr[NN] = run;
}

__global__ void k_gscan() {
    __shared__ int sm[512];
    int t = threadIdx.x;
    int v = (t < GG) ? g_gcnt[t] : 0;
    sm[t] = v;
    __syncthreads();
    for (int off = 1; off < 512; off <<= 1) {
        int u = (t >= off) ? sm[t - off] : 0;
        __syncthreads();
        sm[t] += u;
        __syncthreads();
    }
    if (t < GG) g_goff[t + 1] = sm[t];
    if (t == 0) g_goff[0] = 0;
}

__global__ void k_fill(const void* eidx) {
    int e = blockIdx.x * blockDim.x + threadIdx.x;
    if (e >= EE) return;
    int is64 = g_is64;
    int s = ld_idx(eidx, e, is64);
    int d = ld_idx(eidx, (long long)EE + e, is64);
    int pos = atomicAdd(&g_fill[d], 1);
    int slot = g_ptr[d] + pos;
    g_csr_src[slot] = s;
    g_csr_w[slot] = g_dis[s] * g_dis[d];
}

// ---------------- GEMM: Y[N,128] = f(X)[N,128] @ W[128,128] ----------------
// f = identity (layer 1) or fused BN+ReLU from previous layer stats.
template <bool BN>
__global__ void __launch_bounds__(256) k_gemm(const float* __restrict__ X,
                                              const float* __restrict__ W,
                                              float* __restrict__ Y) {
    __shared__ float Ws[32 * 128];
    __shared__ float Xs[64 * 32];
    int tid = threadIdx.x;
    int row0 = blockIdx.x * 64;
    int colg = (tid & 31) * 4;
    int rowg = (tid >> 5) * 8;
    float acc[8][4];
#pragma unroll
    for (int r = 0; r < 8; r++)
#pragma unroll
        for (int j = 0; j < 4; j++) acc[r][j] = 0.f;

    for (int kt = 0; kt < 4; kt++) {
        int k0 = kt * 32;
        // load W tile 32x128 (4096 floats, 4 float4/thread)
#pragma unroll
        for (int i = 0; i < 4; i++) {
            int q = i * 256 + tid;
            int r = q >> 5;
            int c = (q & 31) * 4;
            float4 v = *(const float4*)(W + (size_t)(k0 + r) * 128 + c);
            *(float4*)(Ws + r * 128 + c) = v;
        }
        // load X tile 64x32 (2048 floats, 2 float4/thread), fused BN+ReLU
#pragma unroll
        for (int i = 0; i < 2; i++) {
            int q = i * 256 + tid;
            int r = q >> 3;
            int c = (q & 7) * 4;
            int gr = row0 + r;
            float4 v = make_float4(0.f, 0.f, 0.f, 0.f);
            if (gr < NN) v = *(const float4*)(X + (size_t)gr * 128 + k0 + c);
            if (BN) {
                int ch = k0 + c;
                v.x = fmaxf(g_bn_a[ch + 0] * v.x + g_bn_b[ch + 0], 0.f);
                v.y = fmaxf(g_bn_a[ch + 1] * v.y + g_bn_b[ch + 1], 0.f);
                v.z = fmaxf(g_bn_a[ch + 2] * v.z + g_bn_b[ch + 2], 0.f);
                v.w = fmaxf(g_bn_a[ch + 3] * v.w + g_bn_b[ch + 3], 0.f);
            }
            *(float4*)(Xs + r * 32 + c) = v;
        }
        __syncthreads();
#pragma unroll
        for (int kk = 0; kk < 8; kk++) {
            float4 xr[8];
#pragma unroll
            for (int r = 0; r < 8; r++)
                xr[r] = *(const float4*)(Xs + (rowg + r) * 32 + kk * 4);
#pragma unroll
            for (int j = 0; j < 4; j++) {
                float4 w = *(const float4*)(Ws + (kk * 4 + j) * 128 + colg);
#pragma unroll
                for (int r = 0; r < 8; r++) {
                    float xv = (j == 0) ? xr[r].x : (j == 1) ? xr[r].y
                               : (j == 2) ? xr[r].z : xr[r].w;
                    acc[r][0] += xv * w.x;
                    acc[r][1] += xv * w.y;
                    acc[r][2] += xv * w.z;
                    acc[r][3] += xv * w.w;
                }
            }
        }
        __syncthreads();
    }
#pragma unroll
    for (int r = 0; r < 8; r++) {
        int gr = row0 + rowg + r;
        if (gr < NN) {
            float4 o = make_float4(acc[r][0], acc[r][1], acc[r][2], acc[r][3]);
            *(float4*)(Y + (size_t)gr * 128 + colg) = o;
        }
    }
}

// ---------------- aggregation: one warp per destination node ----------------
__global__ void k_agg(const float* __restrict__ Hm, const float* __restrict__ bias) {
    int w = (blockIdx.x * blockDim.x + threadIdx.x) >> 5;
    int lane = threadIdx.x & 31;
    if (w >= NN) return;
    int d = w;
    float sd = g_dis[d];
    float ws = sd * sd;  // self-loop norm
    float4 hv = ((const float4*)(Hm + (size_t)d * HH))[lane];
    float4 acc;
    acc.x = hv.x * ws; acc.y = hv.y * ws; acc.z = hv.z * ws; acc.w = hv.w * ws;
    int beg = g_ptr[d], end = g_ptr[d + 1];
    int j = beg;
    for (; j + 4 <= end; j += 4) {
        int s0 = g_csr_src[j + 0], s1 = g_csr_src[j + 1];
        int s2 = g_csr_src[j + 2], s3 = g_csr_src[j + 3];
        float w0 = g_csr_w[j + 0], w1 = g_csr_w[j + 1];
        float w2 = g_csr_w[j + 2], w3 = g_csr_w[j + 3];
        float4 v0 = ((const float4*)(Hm + (size_t)s0 * HH))[lane];
        float4 v1 = ((const float4*)(Hm + (size_t)s1 * HH))[lane];
        float4 v2 = ((const float4*)(Hm + (size_t)s2 * HH))[lane];
        float4 v3 = ((const float4*)(Hm + (size_t)s3 * HH))[lane];
        acc.x += v0.x * w0 + v1.x * w1 + v2.x * w2 + v3.x * w3;
        acc.y += v0.y * w0 + v1.y * w1 + v2.y * w2 + v3.y * w3;
        acc.z += v0.z * w0 + v1.z * w1 + v2.z * w2 + v3.z * w3;
        acc.w += v0.w * w0 + v1.w * w1 + v2.w * w2 + v3.w * w3;
    }
    for (; j < end; j++) {
        int s = g_csr_src[j];
        float wj = g_csr_w[j];
        float4 v = ((const float4*)(Hm + (size_t)s * HH))[lane];
        acc.x += v.x * wj; acc.y += v.y * wj; acc.z += v.z * wj; acc.w += v.w * wj;
    }
    float4 b4 = ((const float4*)bias)[lane];
    acc.x += b4.x; acc.y += b4.y; acc.z += b4.z; acc.w += b4.w;
    ((float4*)(g_agg + (size_t)d * HH))[lane] = acc;
}

// ---------------- BN stats: deterministic two-stage reduction ----------------
__global__ void k_stats_partial(const float* __restrict__ A) {
    int c = threadIdx.x;
    float s = 0.f, q = 0.f;
    for (int r = blockIdx.x; r < NN; r += STAT_NB) {
        float v = A[(size_t)r * HH + c];
        s += v;
        q += v * v;
    }
    g_psum[blockIdx.x * HH + c] = s;
    g_psq[blockIdx.x * HH + c] = q;
}

__global__ void k_stats_final(const float* __restrict__ gam, const float* __restrict__ bet) {
    int c = threadIdx.x;
    float s = 0.f, q = 0.f;
    for (int b = 0; b < STAT_NB; b++) {
        s += g_psum[b * HH + c];
        q += g_psq[b * HH + c];
    }
    float m = s / (float)NN;
    float var = q / (float)NN - m * m;
    float a = gam[c] * rsqrtf(var + EPSBN);
    g_bn_a[c] = a;
    g_bn_b[c] = bet[c] - m * a;
}

// ---------------- pooling (applies layer-3 BN+ReLU on the fly) -------------
__global__ void k_pool(const float* __restrict__ A) {
    int gI = blockIdx.x;
    int c = threadIdx.x;
    int beg = g_goff[gI], end = g_goff[gI + 1];
    float a = g_bn_a[c], b = g_bn_b[c];
    float acc = 0.f;
    for (int r = beg; r < end; r++) {
        float v = A[(size_t)r * HH + c];
        acc += fmaxf(a * v + b, 0.f);
    }
    float cnt = (float)(end - beg);
    g_pooled[gI * HH + c] = acc / fmaxf(cnt, 1.f);
}

// ---------------- FC head ----------------
__global__ void k_fc1(const float* __restrict__ Wf, const float* __restrict__ bf) {
    __shared__ float ps[128];
    int gI = blockIdx.x;
    int c = threadIdx.x;  // 64 threads
    ps[c] = g_pooled[gI * HH + c];
    ps[c + 64] = g_pooled[gI * HH + c + 64];
    __syncthreads();
    float s = bf[c];
#pragma unroll 8
    for (int k = 0; k < 128; k++) s += ps[k] * Wf[k * FC1 + c];
    g_z[gI * FC1 + c] = s;
}

__global__ void k_fcstats(const float* __restrict__ gam, const float* __restrict__ bet) {
    int c = threadIdx.x;  // 64 threads, one block
    float s = 0.f, q = 0.f;
#pragma unroll 4
    for (int r = 0; r < GG; r++) {
        float v = g_z[r * FC1 + c];
        s += v;
        q += v * v;
    }
    float m = s / (float)GG;
    float var = q / (float)GG - m * m;
    float a = gam[c] * rsqrtf(var + EPSBN);
    g_fc_a[c] = a;
    g_fc_b[c] = bet[c] - m * a;
}

__global__ void k_fc2(const float* __restrict__ W2f, const float* __restrict__ b2f,
                      float* __restrict__ out) {
    int gI = blockIdx.x * blockDim.x + threadIdx.x;
    if (gI >= GG) return;
    float s = b2f[0];
#pragma unroll 8
    for (int c = 0; c < FC1; c++) {
        float v = g_z[gI * FC1 + c];
        v = fmaxf(g_fc_a[c] * v + g_fc_b[c], 0.f);
        s += v * W2f[c];
    }
    out[gI] = s;
}

// ---------------- launch ----------------
extern "C" void kernel_launch(void* const* d_in, const int* in_sizes, int n_in,
                              void* d_out, int out_size) {
    const float* x    = (const float*)d_in[0];
    const void*  eidx = d_in[1];
    const void*  batc = d_in[2];
    const float* W1 = (const float*)d_in[3];
    const float* b1 = (const float*)d_in[4];
    const float* g1 = (const float*)d_in[5];
    const float* be1 = (const float*)d_in[6];
    const float* W2 = (const float*)d_in[7];
    const float* b2 = (const float*)d_in[8];
    const float* g2 = (const float*)d_in[9];
    const float* be2 = (const float*)d_in[10];
    const float* W3 = (const float*)d_in[11];
    const float* b3 = (const float*)d_in[12];
    const float* g3 = (const float*)d_in[13];
    const float* be3 = (const float*)d_in[14];
    const float* fcW1 = (const float*)d_in[15];
    const float* fcb1 = (const float*)d_in[16];
    const float* fcg1 = (const float*)d_in[17];
    const float* fcbe1 = (const float*)d_in[18];
    const float* fcW2 = (const float*)d_in[19];
    const float* fcb2 = (const float*)d_in[20];
    float* out = (float*)d_out;

    float *ph = nullptr, *pagg = nullptr;
    cudaGetSymbolAddress((void**)&ph, g_h);
    cudaGetSymbolAddress((void**)&pagg, g_agg);

    const int TB = 256;
    int gemm_blocks = (NN + 63) / 64;
    int agg_blocks = (NN * 32 + TB - 1) / TB;

    k_detect<<<1, 256>>>(eidx);
    k_zero<<<(NN + TB - 1) / TB, TB>>>();
    k_count<<<(EE + TB - 1) / TB, TB>>>(eidx);
    k_gcount<<<(NN + TB - 1) / TB, TB>>>(batc);
    k_scan<<<1, 1024>>>();
    k_gscan<<<1, 512>>>();
    k_fill<<<(EE + TB - 1) / TB, TB>>>(eidx);

    // layer 1
    k_gemm<false><<<gemm_blocks, TB>>>(x, W1, ph);
    k_agg<<<agg_blocks, TB>>>(ph, b1);
    k_stats_partial<<<STAT_NB, 128>>>(pagg);
    k_stats_final<<<1, 128>>>(g1, be1);
    // layer 2 (BN1+ReLU fused into GEMM input load)
    k_gemm<true><<<gemm_blocks, TB>>>(pagg, W2, ph);
    k_agg<<<agg_blocks, TB>>>(ph, b2);
    k_stats_partial<<<STAT_NB, 128>>>(pagg);
    k_stats_final<<<1, 128>>>(g2, be2);
    // layer 3
    k_gemm<true><<<gemm_blocks, TB>>>(pagg, W3, ph);
    k_agg<<<agg_blocks, TB>>>(ph, b3);
    k_stats_partial<<<STAT_NB, 128>>>(pagg);
    k_stats_final<<<1, 128>>>(g3, be3);

    // pool (BN3+ReLU fused) + FC head
    k_pool<<<GG, 128>>>(pagg);
    k_fc1<<<GG, FC1>>>(fcW1, fcb1);
    k_fcstats<<<1, FC1>>>(fcg1, fcbe1);
    k_fc2<<<(GG + TB - 1) / TB, TB>>>(fcW2, fcb2, out);
}

// round 2
// speedup vs baseline: 1.2209x; 1.2209x over previous
#include <cuda_runtime.h>

#define NN 50000
#define EE 800000
#define DDIM 128
#define HH 128
#define GG 500
#define FC1 64
#define EPSBN 1e-5f
#define STAT_NB 240

// ---------------- device scratch (static, no allocation) ----------------
__device__ float g_h[NN * HH];      // GEMM output (pre-aggregation)
__device__ float g_agg[NN * HH];    // aggregated output (pre-BN)
__device__ int   g_cnt[NN];
__device__ int   g_fill[NN];
__device__ int   g_ptr[NN + 1];
__device__ float g_dis[NN];
__device__ int   g_csr_src[EE];
__device__ float g_csr_w[EE];
__device__ float g_psum[STAT_NB * HH];
__device__ float g_psq[STAT_NB * HH];
__device__ float g_bn_a[HH];
__device__ float g_bn_b[HH];
__device__ int   g_goff[GG + 1];
__device__ float g_pooled[GG * HH];
__device__ float g_z[GG * FC1];
__device__ float g_fc_a[FC1];
__device__ float g_fc_b[FC1];
__device__ int   g_is64;

// ---------------- helpers ----------------
__device__ __forceinline__ int ld_idx(const void* p, long long i, int is64) {
    return is64 ? (int)(((const long long*)p)[i]) : ((const int*)p)[i];
}

__device__ __forceinline__ unsigned f2tf32(float v) {
    unsigned o;
    asm("cvt.rna.tf32.f32 %0, %1;" : "=r"(o) : "f"(v));
    return o;
}

// detect whether index arrays are int64 (hi words of first 256 pairs all zero)
__global__ void k_detect(const void* eidx) {
    __shared__ int any;
    const int* p = (const int*)eidx;
    if (threadIdx.x == 0) any = 0;
    __syncthreads();
    if (p[2 * threadIdx.x + 1] != 0) atomicOr(&any, 1);
    __syncthreads();
    if (threadIdx.x == 0) g_is64 = any ? 0 : 1;
}

__global__ void k_zero() {
    int i = blockIdx.x * blockDim.x + threadIdx.x;
    if (i < NN) { g_cnt[i] = 0; g_fill[i] = 0; }
}

__global__ void k_count(const void* eidx) {
    int e = blockIdx.x * blockDim.x + threadIdx.x;
    if (e >= EE) return;
    int is64 = g_is64;
    int d = ld_idx(eidx, (long long)EE + e, is64);
    atomicAdd(&g_cnt[d], 1);
}

// batch is sorted: graph offsets via binary search (no atomics, no scan)
__global__ void k_gbounds(const void* batch) {
    int gI = blockIdx.x * blockDim.x + threadIdx.x;
    if (gI > GG) return;
    int is64 = g_is64;
    int lo = 0, hi = NN;
    while (lo < hi) {
        int mid = (lo + hi) >> 1;
        int b = ld_idx(batch, mid, is64);
        if (b < gI) lo = mid + 1; else hi = mid;
    }
    g_goff[gI] = lo;
}

// single-block exclusive scan over N node counts; also writes dis = rsqrt(deg)
__global__ void k_scan() {
    const int CH = 49;  // 1024*49 = 50176 >= NN
    __shared__ int sm[1024];
    int t = threadIdx.x;
    int base = t * CH;
    int len = NN - base;
    if (len < 0) len = 0;
    if (len > CH) len = CH;
    int s = 0;
    for (int i = 0; i < len; i++) s += g_cnt[base + i];
    sm[t] = s;
    __syncthreads();
    for (int off = 1; off < 1024; off <<= 1) {
        int v = (t >= off) ? sm[t - off] : 0;
        __syncthreads();
        sm[t] += v;
        __syncthreads();
    }
    int run = sm[t] - s;  // exclusive prefix
    for (int i = 0; i < len; i++) {
        int c = g_cnt[base + i];
        g_ptr[base + i] = run;
        g_dis[base + i] = rsqrtf((float)(c + 1));  // +1 self loop, deg>=1
        run += c;
    }
    if (base < NN && base + CH >= NN) g_ptr[NN] = run;
}

__global__ void k_fill(const void* eidx) {
    int e = blockIdx.x * blockDim.x + threadIdx.x;
    if (e >= EE) return;
    int is64 = g_is64;
    int s = ld_idx(eidx, e, is64);
    int d = ld_idx(eidx, (long long)EE + e, is64);
    int pos = atomicAdd(&g_fill[d], 1);
    int slot = g_ptr[d] + pos;
    g_csr_src[slot] = s;
    g_csr_w[slot] = g_dis[s] * g_dis[d];
}

// ---------------- TF32 tensor-core GEMM ----------------
// Y[N,128] = f(X)[N,128] @ W[128,128]; f = identity or fused BN+ReLU.
// Block: 64 rows x 128 cols, 256 threads = 8 warps in 2(M) x 4(N) grid.
// Warp tile: 32x32 = 2 m-tiles x 4 n-tiles of m16n8k8.
#define XS_STRIDE 132
#define WS_STRIDE 136

template <bool BN>
__global__ void __launch_bounds__(256) k_gemm_tc(const float* __restrict__ X,
                                                const float* __restrict__ W,
                                                float* __restrict__ Y) {
    extern __shared__ float smem[];
    float* Xs = smem;                    // [64][XS_STRIDE]
    float* Ws = smem + 64 * XS_STRIDE;   // [128][WS_STRIDE]
    int tid = threadIdx.x;
    int row0 = blockIdx.x * 64;

    // load X tile 64x128 (2048 float4), fused BN+ReLU, tf32 rounding
#pragma unroll
    for (int i = 0; i < 8; i++) {
        int q = i * 256 + tid;
        int r = q >> 5;
        int c = (q & 31) * 4;
        int gr = row0 + r;
        float4 v = make_float4(0.f, 0.f, 0.f, 0.f);
        if (gr < NN) v = *(const float4*)(X + (size_t)gr * 128 + c);
        if (BN) {
            v.x = fmaxf(g_bn_a[c + 0] * v.x + g_bn_b[c + 0], 0.f);
            v.y = fmaxf(g_bn_a[c + 1] * v.y + g_bn_b[c + 1], 0.f);
            v.z = fmaxf(g_bn_a[c + 2] * v.z + g_bn_b[c + 2], 0.f);
            v.w = fmaxf(g_bn_a[c + 3] * v.w + g_bn_b[c + 3], 0.f);
        }
        float* d = Xs + r * XS_STRIDE + c;
        d[0] = __uint_as_float(f2tf32(v.x));
        d[1] = __uint_as_float(f2tf32(v.y));
        d[2] = __uint_as_float(f2tf32(v.z));
        d[3] = __uint_as_float(f2tf32(v.w));
    }
    // load W tile 128x128 (4096 float4 / 256 thr = 16 each), tf32 rounding
#pragma unroll
    for (int i = 0; i < 16; i++) {
        int q = i * 256 + tid;
        int r = q >> 5;
        int c = (q & 31) * 4;
        float4 v = *(const float4*)(W + (size_t)r * 128 + c);
        float* d = Ws + r * WS_STRIDE + c;
        d[0] = __uint_as_float(f2tf32(v.x));
        d[1] = __uint_as_float(f2tf32(v.y));
        d[2] = __uint_as_float(f2tf32(v.z));
        d[3] = __uint_as_float(f2tf32(v.w));
    }
    __syncthreads();

    int wid = tid >> 5;
    int lane = tid & 31;
    int mwid = wid >> 2;   // 0..1 -> rows mwid*32
    int nwid = wid & 3;    // 0..3 -> cols nwid*32
    int g = lane >> 2;     // 0..7
    int tg = lane & 3;     // 0..3

    float acc[2][4][4];
#pragma unroll
    for (int mi = 0; mi < 2; mi++)
#pragma unroll
        for (int ni = 0; ni < 4; ni++)
#pragma unroll
            for (int j = 0; j < 4; j++) acc[mi][ni][j] = 0.f;

#pragma unroll
    for (int k0 = 0; k0 < 128; k0 += 8) {
        unsigned a[2][4];
#pragma unroll
        for (int mi = 0; mi < 2; mi++) {
            int rb = mwid * 32 + mi * 16;
            a[mi][0] = __float_as_uint(Xs[(rb + g) * XS_STRIDE + k0 + tg]);
            a[mi][1] = __float_as_uint(Xs[(rb + g + 8) * XS_STRIDE + k0 + tg]);
            a[mi][2] = __float_as_uint(Xs[(rb + g) * XS_STRIDE + k0 + tg + 4]);
            a[mi][3] = __float_as_uint(Xs[(rb + g + 8) * XS_STRIDE + k0 + tg + 4]);
        }
        unsigned b[4][2];
#pragma unroll
        for (int ni = 0; ni < 4; ni++) {
            int cb = nwid * 32 + ni * 8;
            b[ni][0] = __float_as_uint(Ws[(k0 + tg) * WS_STRIDE + cb + g]);
            b[ni][1] = __float_as_uint(Ws[(k0 + tg + 4) * WS_STRIDE + cb + g]);
        }
#pragma unroll
        for (int mi = 0; mi < 2; mi++)
#pragma unroll
            for (int ni = 0; ni < 4; ni++) {
                asm volatile(
                    "mma.sync.aligned.m16n8k8.row.col.f32.tf32.tf32.f32 "
                    "{%0,%1,%2,%3}, {%4,%5,%6,%7}, {%8,%9}, {%0,%1,%2,%3};"
                    : "+f"(acc[mi][ni][0]), "+f"(acc[mi][ni][1]),
                      "+f"(acc[mi][ni][2]), "+f"(acc[mi][ni][3])
                    : "r"(a[mi][0]), "r"(a[mi][1]), "r"(a[mi][2]), "r"(a[mi][3]),
                      "r"(b[ni][0]), "r"(b[ni][1]));
            }
    }

    // write out (float2 per fragment half)
#pragma unroll
    for (int mi = 0; mi < 2; mi++) {
#pragma unroll
        for (int ni = 0; ni < 4; ni++) {
            int col = nwid * 32 + ni * 8 + tg * 2;
            int r1 = row0 + mwid * 32 + mi * 16 + g;
            int r2 = r1 + 8;
            if (r1 < NN)
                *(float2*)(Y + (size_t)r1 * 128 + col) =
                    make_float2(acc[mi][ni][0], acc[mi][ni][1]);
            if (r2 < NN)
                *(float2*)(Y + (size_t)r2 * 128 + col) =
                    make_float2(acc[mi][ni][2], acc[mi][ni][3]);
        }
    }
}

// ---------------- aggregation: one warp per destination node ----------------
__global__ void k_agg(const float* __restrict__ Hm, const float* __restrict__ bias) {
    int w = (blockIdx.x * blockDim.x + threadIdx.x) >> 5;
    int lane = threadIdx.x & 31;
    if (w >= NN) return;
    int d = w;
    float sd = g_dis[d];
    float ws = sd * sd;  // self-loop norm
    float4 hv = ((const float4*)(Hm + (size_t)d * HH))[lane];
    float4 acc;
    acc.x = hv.x * ws; acc.y = hv.y * ws; acc.z = hv.z * ws; acc.w = hv.w * ws;
    int beg = g_ptr[d], end = g_ptr[d + 1];
    int j = beg;
    for (; j + 4 <= end; j += 4) {
        int s0 = g_csr_src[j + 0], s1 = g_csr_src[j + 1];
        int s2 = g_csr_src[j + 2], s3 = g_csr_src[j + 3];
        float w0 = g_csr_w[j + 0], w1 = g_csr_w[j + 1];
        float w2 = g_csr_w[j + 2], w3 = g_csr_w[j + 3];
        float4 v0 = ((const float4*)(Hm + (size_t)s0 * HH))[lane];
        float4 v1 = ((const float4*)(Hm + (size_t)s1 * HH))[lane];
        float4 v2 = ((const float4*)(Hm + (size_t)s2 * HH))[lane];
        float4 v3 = ((const float4*)(Hm + (size_t)s3 * HH))[lane];
        acc.x += v0.x * w0 + v1.x * w1 + v2.x * w2 + v3.x * w3;
        acc.y += v0.y * w0 + v1.y * w1 + v2.y * w2 + v3.y * w3;
        acc.z += v0.z * w0 + v1.z * w1 + v2.z * w2 + v3.z * w3;
        acc.w += v0.w * w0 + v1.w * w1 + v2.w * w2 + v3.w * w3;
    }
    for (; j < end; j++) {
        int s = g_csr_src[j];
        float wj = g_csr_w[j];
        float4 v = ((const float4*)(Hm + (size_t)s * HH))[lane];
        acc.x += v.x * wj; acc.y += v.y * wj; acc.z += v.z * wj; acc.w += v.w * wj;
    }
    float4 b4 = ((const float4*)bias)[lane];
    acc.x += b4.x; acc.y += b4.y; acc.z += b4.z; acc.w += b4.w;
    ((float4*)(g_agg + (size_t)d * HH))[lane] = acc;
}

// ---------------- BN stats: deterministic two-stage reduction ----------------
__global__ void k_stats_partial(const float* __restrict__ A) {
    int c = threadIdx.x;
    float s = 0.f, q = 0.f;
    for (int r = blockIdx.x; r < NN; r += STAT_NB) {
        float v = A[(size_t)r * HH + c];
        s += v;
        q += v * v;
    }
    g_psum[blockIdx.x * HH + c] = s;
    g_psq[blockIdx.x * HH + c] = q;
}

__global__ void k_stats_final(const float* __restrict__ gam, const float* __restrict__ bet) {
    int c = threadIdx.x;
    float s = 0.f, q = 0.f;
    for (int b = 0; b < STAT_NB; b++) {
        s += g_psum[b * HH + c];
        q += g_psq[b * HH + c];
    }
    float m = s / (float)NN;
    float var = q / (float)NN - m * m;
    float a = gam[c] * rsqrtf(var + EPSBN);
    g_bn_a[c] = a;
    g_bn_b[c] = bet[c] - m * a;
}

// ---------------- pooling (applies layer-3 BN+ReLU on the fly) -------------
__global__ void k_pool(const float* __restrict__ A) {
    int gI = blockIdx.x;
    int c = threadIdx.x;
    int beg = g_goff[gI], end = g_goff[gI + 1];
    float a = g_bn_a[c], b = g_bn_b[c];
    float acc = 0.f;
    for (int r = beg; r < end; r++) {
        float v = A[(size_t)r * HH + c];
        acc += fmaxf(a * v + b, 0.f);
    }
    float cnt = (float)(end - beg);
    g_pooled[gI * HH + c] = acc / fmaxf(cnt, 1.f);
}

// ---------------- FC head ----------------
__global__ void k_fc1(const float* __restrict__ Wf, const float* __restrict__ bf) {
    __shared__ float ps[128];
    int gI = blockIdx.x;
    int c = threadIdx.x;  // 64 threads
    ps[c] = g_pooled[gI * HH + c];
    ps[c + 64] = g_pooled[gI * HH + c + 64];
    __syncthreads();
    float s = bf[c];
#pragma unroll 8
    for (int k = 0; k < 128; k++) s += ps[k] * Wf[k * FC1 + c];
    g_z[gI * FC1 + c] = s;
}

__global__ void k_fcstats(const float* __restrict__ gam, const float* __restrict__ bet) {
    int c = threadIdx.x;  // 64 threads, one block
    float s = 0.f, q = 0.f;
#pragma unroll 4
    for (int r = 0; r < GG; r++) {
        float v = g_z[r * FC1 + c];
        s += v;
        q += v * v;
    }
    float m = s / (float)GG;
    float var = q / (float)GG - m * m;
    float a = gam[c] * rsqrtf(var + EPSBN);
    g_fc_a[c] = a;
    g_fc_b[c] = bet[c] - m * a;
}

__global__ void k_fc2(const float* __restrict__ W2f, const float* __restrict__ b2f,
                      float* __restrict__ out) {
    int gI = blockIdx.x * blockDim.x + threadIdx.x;
    if (gI >= GG) return;
    float s = b2f[0];
#pragma unroll 8
    for (int c = 0; c < FC1; c++) {
        float v = g_z[gI * FC1 + c];
        v = fmaxf(g_fc_a[c] * v + g_fc_b[c], 0.f);
        s += v * W2f[c];
    }
    out[gI] = s;
}

// ---------------- launch ----------------
extern "C" void kernel_launch(void* const* d_in, const int* in_sizes, int n_in,
                              void* d_out, int out_size) {
    const float* x    = (const float*)d_in[0];
    const void*  eidx = d_in[1];
    const void*  batc = d_in[2];
    const float* W1 = (const float*)d_in[3];
    const float* b1 = (const float*)d_in[4];
    const float* g1 = (const float*)d_in[5];
    const float* be1 = (const float*)d_in[6];
    const float* W2 = (const float*)d_in[7];
    const float* b2 = (const float*)d_in[8];
    const float* g2 = (const float*)d_in[9];
    const float* be2 = (const float*)d_in[10];
    const float* W3 = (const float*)d_in[11];
    const float* b3 = (const float*)d_in[12];
    const float* g3 = (const float*)d_in[13];
    const float* be3 = (const float*)d_in[14];
    const float* fcW1 = (const float*)d_in[15];
    const float* fcb1 = (const float*)d_in[16];
    const float* fcg1 = (const float*)d_in[17];
    const float* fcbe1 = (const float*)d_in[18];
    const float* fcW2 = (const float*)d_in[19];
    const float* fcb2 = (const float*)d_in[20];
    float* out = (float*)d_out;

    float *ph = nullptr, *pagg = nullptr;
    cudaGetSymbolAddress((void**)&ph, g_h);
    cudaGetSymbolAddress((void**)&pagg, g_agg);

    const int TB = 256;
    const int gemm_blocks = (NN + 63) / 64;
    const int gemm_smem = (64 * XS_STRIDE + 128 * WS_STRIDE) * 4;
    static int smem_set = 0;
    if (!smem_set) {
        cudaFuncSetAttribute(k_gemm_tc<false>,
                             cudaFuncAttributeMaxDynamicSharedMemorySize, gemm_smem);
        cudaFuncSetAttribute(k_gemm_tc<true>,
                             cudaFuncAttributeMaxDynamicSharedMemorySize, gemm_smem);
        smem_set = 1;
    }
    int agg_blocks = (NN * 32 + TB - 1) / TB;

    k_detect<<<1, 256>>>(eidx);
    k_zero<<<(NN + TB - 1) / TB, TB>>>();
    k_count<<<(EE + TB - 1) / TB, TB>>>(eidx);
    k_gbounds<<<2, 512>>>(batc);
    k_scan<<<1, 1024>>>();
    k_fill<<<(EE + TB - 1) / TB, TB>>>(eidx);

    // layer 1
    k_gemm_tc<false><<<gemm_blocks, TB, gemm_smem>>>(x, W1, ph);
    k_agg<<<agg_blocks, TB>>>(ph, b1);
    k_stats_partial<<<STAT_NB, 128>>>(pagg);
    k_stats_final<<<1, 128>>>(g1, be1);
    // layer 2 (BN1+ReLU fused into GEMM input load)
    k_gemm_tc<true><<<gemm_blocks, TB, gemm_smem>>>(pagg, W2, ph);
    k_agg<<<agg_blocks, TB>>>(ph, b2);
    k_stats_partial<<<STAT_NB, 128>>>(pagg);
    k_stats_final<<<1, 128>>>(g2, be2);
    // layer 3
    k_gemm_tc<true><<<gemm_blocks, TB, gemm_smem>>>(pagg, W3, ph);
    k_agg<<<agg_blocks, TB>>>(ph, b3);
    k_stats_partial<<<STAT_NB, 128>>>(pagg);
    k_stats_final<<<1, 128>>>(g3, be3);

    // pool (BN3+ReLU fused) + FC head
    k_pool<<<GG, 128>>>(pagg);
    k_fc1<<<GG, FC1>>>(fcW1, fcb1);
    k_fcstats<<<1, FC1>>>(fcg1, fcbe1);
    k_fc2<<<(GG + TB - 1) / TB, TB>>>(fcW2, fcb2, out);
}